// round 10
// baseline (speedup 1.0000x reference)
#include <cuda_runtime.h>
#include <math.h>

// Problem constants
#define BB 32
#define TT 1000
#define DD 640
#define VV 1024
#define NB 128   // CTAs (<= 148 SMs -> all co-resident, safe for sw grid barrier)
#define NT 512   // 16 warps per CTA (128 regs/thread cap)

typedef unsigned long long u64;

// ---------------- persistent device state (no allocations allowed) ----------
__device__ __align__(16) float g_hbuf[2][BB][DD];   // double-buffered h (== out_pn)
__device__ __align__(16) float g_c[BB][DD];
__device__ __align__(16) float g_z[BB][DD];
__device__ __align__(16) float4 g_part[BB][NB];     // (max, sumexp, argmax, -) per CTA
__device__ float g_score[BB];
__device__ u64   g_bar = 0ull;                      // monotone barrier counter

// ---------------- packed fp32x2 helpers (full-rate fp32 path on Blackwell) --
#define FFMA2(acc, a, b) \
    asm("fma.rn.f32x2 %0, %1, %2, %0;" : "+l"(acc) : "l"(a), "l"(b))

__device__ __forceinline__ float usum(u64 u) {
    float x, y;
    asm("mov.b64 {%0,%1}, %2;" : "=f"(x), "=f"(y) : "l"(u));
    return x + y;
}

// ---------------- grid barrier (counting, no reset; deterministic count per
// launch so graph replays stay consistent) ----------------------------------
__device__ __forceinline__ void grid_barrier() {
    __syncthreads();
    if (threadIdx.x == 0) {
        __threadfence();
        u64 m = atomicAdd(&g_bar, 1ull) + 1ull;
        u64 goal = ((m + (u64)NB - 1ull) / (u64)NB) * (u64)NB;
        while (*((volatile u64*)&g_bar) < goal) { }
        __threadfence();
    }
    __syncthreads();
}

__device__ __forceinline__ float wred(float v) {
    v += __shfl_xor_sync(0xffffffffu, v, 16);
    v += __shfl_xor_sync(0xffffffffu, v, 8);
    v += __shfl_xor_sync(0xffffffffu, v, 4);
    v += __shfl_xor_sync(0xffffffffu, v, 2);
    v += __shfl_xor_sync(0xffffffffu, v, 1);
    return v;
}

__device__ __forceinline__ float sigf(float x) { return 1.0f / (1.0f + expf(-x)); }

// Order-independent logsumexp/argmax merge (first-index on exact ties).
__device__ __forceinline__ void pmerge(float& m, float& s, int& mi,
                                       float m2, float s2, int i2) {
    if (m2 > m || (m2 == m && i2 < mi)) {
        s = s2 + s * expf(m - m2);
        m = m2; mi = i2;
    } else {
        s = s + s2 * expf(m2 - m);
    }
}

// ============================================================================
// Phase Z: z[b][j] = tanh( tn[b][t]·W_tn[j] + h[b]·W_pn[j] + b_joint[j] )
// 16 warps: warp owns 2 batches; CTA owns 5 j-columns; lanes split K (float4).
// ============================================================================
__device__ __forceinline__ void z_phase(
    int cc, int wid, int lane, int t, int par,
    const float* __restrict__ tn, const float* __restrict__ W_tn,
    const float* __restrict__ W_pn, const float* __restrict__ b_joint)
{
    const int j0 = cc * 5;
    const int b0 = wid * 2;
    u64 acc[2][5];
#pragma unroll
    for (int i = 0; i < 2; i++)
#pragma unroll
        for (int j = 0; j < 5; j++) acc[i][j] = 0ull;

    for (int kc = 0; kc < DD; kc += 128) {
        const int k = kc + lane * 4;
        ulonglong2 a1[2], a2[2];
#pragma unroll
        for (int i = 0; i < 2; i++) {
            a1[i] = *(const ulonglong2*)(tn + ((size_t)(b0 + i) * TT + (size_t)t) * DD + k);
            a2[i] = *(const ulonglong2*)(&g_hbuf[par][b0 + i][k]);
        }
#pragma unroll
        for (int j = 0; j < 5; j++) {
            ulonglong2 w1 = *(const ulonglong2*)(W_tn + (size_t)(j0 + j) * DD + k);
            ulonglong2 w2 = *(const ulonglong2*)(W_pn + (size_t)(j0 + j) * DD + k);
#pragma unroll
            for (int i = 0; i < 2; i++) {
                FFMA2(acc[i][j], a1[i].x, w1.x);
                FFMA2(acc[i][j], a1[i].y, w1.y);
                FFMA2(acc[i][j], a2[i].x, w2.x);
                FFMA2(acc[i][j], a2[i].y, w2.y);
            }
        }
    }
    if (true) {
        float r[2][5];
#pragma unroll
        for (int i = 0; i < 2; i++)
#pragma unroll
            for (int j = 0; j < 5; j++) r[i][j] = wred(usum(acc[i][j]));
        if (lane == 0) {
#pragma unroll
            for (int i = 0; i < 2; i++)
#pragma unroll
                for (int j = 0; j < 5; j++)
                    g_z[b0 + i][j0 + j] = tanhf(r[i][j] + b_joint[j0 + j]);
        }
    }
}

// ============================================================================
// Phase L: logits for CTA's 8 v-columns; emit (max, sumexp, argmax) partial
// per (batch, CTA) instead of materializing logits. Warp owns 2 batches.
// ============================================================================
__device__ __forceinline__ void l_phase(
    int cc, int wid, int lane,
    const float* __restrict__ W_out, const float* __restrict__ b_out)
{
    const int v0 = cc * 8;
    const int b0 = wid * 2;
    u64 acc[2][8];
#pragma unroll
    for (int i = 0; i < 2; i++)
#pragma unroll
        for (int v = 0; v < 8; v++) acc[i][v] = 0ull;

    for (int kc = 0; kc < DD; kc += 128) {
        const int k = kc + lane * 4;
        ulonglong2 zv[2];
#pragma unroll
        for (int i = 0; i < 2; i++) zv[i] = *(const ulonglong2*)(&g_z[b0 + i][k]);
#pragma unroll
        for (int v = 0; v < 8; v++) {
            ulonglong2 wv = *(const ulonglong2*)(W_out + (size_t)(v0 + v) * DD + k);
#pragma unroll
            for (int i = 0; i < 2; i++) {
                FFMA2(acc[i][v], zv[i].x, wv.x);
                FFMA2(acc[i][v], zv[i].y, wv.y);
            }
        }
    }
    float r[2][8];
#pragma unroll
    for (int i = 0; i < 2; i++)
#pragma unroll
        for (int v = 0; v < 8; v++) r[i][v] = wred(usum(acc[i][v]));

    if (lane == 0) {
#pragma unroll
        for (int i = 0; i < 2; i++) {
            float vals[8];
#pragma unroll
            for (int v = 0; v < 8; v++) vals[v] = r[i][v] + b_out[v0 + v];
            float m = vals[0]; int mi = v0;
#pragma unroll
            for (int v = 1; v < 8; v++)
                if (vals[v] > m) { m = vals[v]; mi = v0 + v; }  // lowest idx on tie
            float s = 0.f;
#pragma unroll
            for (int v = 0; v < 8; v++) s += expf(vals[v] - m);
            g_part[b0 + i][cc] = make_float4(m, s, (float)mi, 0.f);
        }
    }
}

// ============================================================================
// Phase CG: (a) every CTA redundantly merges the 128 partials per batch
// (bitwise-deterministic) -> smem tok/nonblank; CTA 0 writes tokens + score.
// (b) LSTM gates GEMV: warps 0-7 gates {i,f}, warps 8-15 gates {g,o}, each
// warp 4 batches x 10 rows. Each K-chunk is split into an x-half-pass then an
// h-half-pass sharing one staging buffer (keeps live regs ~112 < 128 cap).
// ============================================================================
__device__ __forceinline__ void cg_phase(
    int cc, int wid, int lane, int t, int rp, int prime, int do_lstm,
    const float* __restrict__ E, const float* __restrict__ W_ih,
    const float* __restrict__ W_hh, const float* __restrict__ b_lstm,
    float* __restrict__ out, float* sg, int* s_tok, int* s_nb)
{
    if (!prime) {
        // warp wid merges partials for batches 2*wid, 2*wid+1
#pragma unroll
        for (int bi = 0; bi < 2; bi++) {
            const int b = wid * 2 + bi;
            float4 q = g_part[b][lane];
            float m = q.x, s = q.y; int mi = (int)q.z;
#pragma unroll
            for (int r = 1; r < 4; r++) {
                float4 p = g_part[b][lane + 32 * r];
                pmerge(m, s, mi, p.x, p.y, (int)p.z);
            }
#pragma unroll
            for (int d = 16; d > 0; d >>= 1) {
                float m2 = __shfl_xor_sync(0xffffffffu, m, d);
                float s2 = __shfl_xor_sync(0xffffffffu, s, d);
                int   i2 = __shfl_xor_sync(0xffffffffu, mi, d);
                pmerge(m, s, mi, m2, s2, i2);
            }
            if (lane == 0) {
                const int nb = (mi != 0);
                s_nb[b] = nb;
                s_tok[b] = nb ? mi : 0;   // blank-step LSTM result is discarded
                if (cc == 0) {
                    out[(size_t)b * TT + t] = nb ? (float)mi : 0.0f;
                    if (nb) g_score[b] += -logf(s);  // logp at argmax
                }
            }
        }
    } else {
        if (wid == 0) { s_tok[lane] = 0; s_nb[lane] = 1; }
    }
    __syncthreads();
    if (!do_lstm) return;

    const int j0 = cc * 5;
    const int pass = wid >> 3;          // 0: gates i,f   1: gates g,o
    const int b0 = (wid & 7) * 4;
    u64 acc[4][10];
#pragma unroll
    for (int i = 0; i < 4; i++)
#pragma unroll
        for (int o = 0; o < 10; o++) acc[i][o] = 0ull;

    const float* xp[4];
#pragma unroll
    for (int i = 0; i < 4; i++) xp[i] = E + (size_t)s_tok[b0 + i] * DD;

#pragma unroll 1
    for (int kc = 0; kc < DD; kc += 128) {
        const int k = kc + lane * 4;
        ulonglong2 av[4];
        // ---- half-pass A: x · W_ih ----
#pragma unroll
        for (int i = 0; i < 4; i++) av[i] = *(const ulonglong2*)(xp[i] + k);
#pragma unroll
        for (int o = 0; o < 10; o++) {
            const int row = (pass * 2 + o / 5) * DD + j0 + (o % 5);
            ulonglong2 w = *(const ulonglong2*)(W_ih + (size_t)row * DD + k);
#pragma unroll
            for (int i = 0; i < 4; i++) {
                FFMA2(acc[i][o], av[i].x, w.x);
                FFMA2(acc[i][o], av[i].y, w.y);
            }
        }
        // ---- half-pass B: h · W_hh ----
#pragma unroll
        for (int i = 0; i < 4; i++) av[i] = *(const ulonglong2*)(&g_hbuf[rp][b0 + i][k]);
#pragma unroll
        for (int o = 0; o < 10; o++) {
            const int row = (pass * 2 + o / 5) * DD + j0 + (o % 5);
            ulonglong2 w = *(const ulonglong2*)(W_hh + (size_t)row * DD + k);
#pragma unroll
            for (int i = 0; i < 4; i++) {
                FFMA2(acc[i][o], av[i].x, w.x);
                FFMA2(acc[i][o], av[i].y, w.y);
            }
        }
    }
    {
        float r;
#pragma unroll
        for (int i = 0; i < 4; i++)
#pragma unroll
            for (int o = 0; o < 10; o++) {
                r = wred(usum(acc[i][o]));
                if (lane == 0) sg[(b0 + i) * 20 + pass * 10 + o] = r;
            }
    }
    __syncthreads();

    // pointwise LSTM update: warps 0-7, lanes 0-19 -> (batch, j) pairs
    if (wid < 8 && lane < 20) {
        const int i = lane / 5, jj = lane - i * 5;
        const int b = wid * 4 + i;
        const int j = j0 + jj;
        if (s_nb[b]) {
            float gi = sg[b * 20 + jj]      + b_lstm[j];
            float gf = sg[b * 20 + 5 + jj]  + b_lstm[DD + j];
            float gg = sg[b * 20 + 10 + jj] + b_lstm[2 * DD + j];
            float go = sg[b * 20 + 15 + jj] + b_lstm[3 * DD + j];
            float cn = sigf(gf) * g_c[b][j] + sigf(gi) * tanhf(gg);
            float hn = sigf(go) * tanhf(cn);
            g_c[b][j] = cn;
            g_hbuf[rp ^ 1][b][j] = hn;
        } else {
            g_hbuf[rp ^ 1][b][j] = g_hbuf[rp][b][j];
        }
    }
}

// ============================================================================
// Persistent kernel: init -> prime LSTM -> 1000 x {Z | L | CG} (3 barriers/step)
// ============================================================================
__global__ void __launch_bounds__(NT, 1)
rnnt_decode_kernel(const float* __restrict__ tn,     const float* __restrict__ E,
                   const float* __restrict__ W_ih,   const float* __restrict__ W_hh,
                   const float* __restrict__ b_lstm, const float* __restrict__ W_tn,
                   const float* __restrict__ W_pn,   const float* __restrict__ b_joint,
                   const float* __restrict__ W_out,  const float* __restrict__ b_out,
                   float* __restrict__ out)
{
    __shared__ float sg[BB * 20];
    __shared__ int   s_tok[BB];
    __shared__ int   s_nb[BB];

    const int cc   = blockIdx.x;
    const int tid  = threadIdx.x;
    const int lane = tid & 31;
    const int wid  = tid >> 5;

    // ---- per-launch state init (deterministic across graph replays) ----
    for (int i = cc * NT + tid; i < BB * DD; i += NB * NT) {
        (&g_hbuf[0][0][0])[i] = 0.f;
        (&g_c[0][0])[i]       = 0.f;
    }
    if (cc == 0 && tid < BB) g_score[tid] = 0.f;
    grid_barrier();

    // ---- priming LSTM step: h,c = lstm(E[BLANK], 0, 0) ----
    int par = 0;
    cg_phase(cc, wid, lane, 0, par, /*prime=*/1, /*do_lstm=*/1,
             E, W_ih, W_hh, b_lstm, out, sg, s_tok, s_nb);
    par ^= 1;
    grid_barrier();

    // ---- sequential decode ----
    for (int t = 0; t < TT; t++) {
        z_phase(cc, wid, lane, t, par, tn, W_tn, W_pn, b_joint);
        grid_barrier();
        l_phase(cc, wid, lane, W_out, b_out);
        grid_barrier();
        cg_phase(cc, wid, lane, t, par, /*prime=*/0,
                 /*do_lstm=*/(t < TT - 1) ? 1 : 0,
                 E, W_ih, W_hh, b_lstm, out, sg, s_tok, s_nb);
        if (t < TT - 1) { par ^= 1; grid_barrier(); }
    }

    // ---- epilogue: scores + mean(exp(score)) (CTA 0 owns g_score) ----
    __syncthreads();
    if (cc == 0) {
        if (tid < BB) out[(size_t)BB * TT + tid] = g_score[tid];
        if (tid == 0) {
            float s = 0.f;
            for (int b = 0; b < BB; b++) s += expf(g_score[b]);
            out[(size_t)BB * TT + BB] = s / (float)BB;
        }
    }
}

extern "C" void kernel_launch(void* const* d_in, const int* in_sizes, int n_in,
                              void* d_out, int out_size)
{
    (void)in_sizes; (void)n_in; (void)out_size;
    const float* tn      = (const float*)d_in[0];
    const float* E       = (const float*)d_in[1];
    const float* W_ih    = (const float*)d_in[2];
    const float* W_hh    = (const float*)d_in[3];
    const float* b_lstm  = (const float*)d_in[4];
    const float* W_tn    = (const float*)d_in[5];
    const float* W_pn    = (const float*)d_in[6];
    const float* b_joint = (const float*)d_in[7];
    const float* W_out   = (const float*)d_in[8];
    const float* b_out   = (const float*)d_in[9];
    float* out = (float*)d_out;

    rnnt_decode_kernel<<<NB, NT>>>(tn, E, W_ih, W_hh, b_lstm,
                                   W_tn, W_pn, b_joint, W_out, b_out, out);
}

// round 11
// speedup vs baseline: 1.0469x; 1.0469x over previous
#include <cuda_runtime.h>
#include <math.h>

// Problem constants
#define BB 32
#define TT 1000
#define DD 640
#define VV 1024
#define NB 128   // CTAs (<= 148 SMs -> all co-resident, safe for sw grid barrier)
#define NT 512   // 16 warps per CTA (128 regs/thread cap)

typedef unsigned long long u64;

// ---------------- persistent device state (no allocations allowed) ----------
__device__ __align__(16) float g_hbuf[2][BB][DD];   // double-buffered h (== out_pn)
__device__ __align__(16) float g_c[BB][DD];
__device__ __align__(16) float g_z[BB][DD];
__device__ __align__(16) float4 g_part[BB][NB];     // (max, sumexp, argmax, -) per CTA
__device__ float g_score[BB];
__device__ u64   g_bar = 0ull;                      // monotone barrier counter

// ---------------- grid barrier (counting, no reset; deterministic count per
// launch so graph replays stay consistent) ----------------------------------
__device__ __forceinline__ void grid_barrier() {
    __syncthreads();
    if (threadIdx.x == 0) {
        __threadfence();
        u64 m = atomicAdd(&g_bar, 1ull) + 1ull;
        u64 goal = ((m + (u64)NB - 1ull) / (u64)NB) * (u64)NB;
        while (*((volatile u64*)&g_bar) < goal) { }
        __threadfence();
    }
    __syncthreads();
}

__device__ __forceinline__ float wred(float v) {
    v += __shfl_xor_sync(0xffffffffu, v, 16);
    v += __shfl_xor_sync(0xffffffffu, v, 8);
    v += __shfl_xor_sync(0xffffffffu, v, 4);
    v += __shfl_xor_sync(0xffffffffu, v, 2);
    v += __shfl_xor_sync(0xffffffffu, v, 1);
    return v;
}

__device__ __forceinline__ float sigf(float x) { return 1.0f / (1.0f + expf(-x)); }

// Order-independent logsumexp/argmax merge (first-index on exact ties).
__device__ __forceinline__ void pmerge(float& m, float& s, int& mi,
                                       float m2, float s2, int i2) {
    if (m2 > m || (m2 == m && i2 < mi)) {
        s = s2 + s * expf(m - m2);
        m = m2; mi = i2;
    } else {
        s = s + s2 * expf(m2 - m);
    }
}

// ============================================================================
// Phase Z: z[b][j] = tanh( tn[b][t]·W_tn[j] + h[b]·W_pn[j] + b_joint[j] )
// 16 warps: warp owns 2 batches; CTA owns 5 j-columns; lanes split K (float4).
// ============================================================================
__device__ __forceinline__ void z_phase(
    int cc, int wid, int lane, int t, int par,
    const float* __restrict__ tn, const float* __restrict__ W_tn,
    const float* __restrict__ W_pn, const float* __restrict__ b_joint)
{
    const int j0 = cc * 5;
    const int b0 = wid * 2;
    float acc[2][5];
#pragma unroll
    for (int i = 0; i < 2; i++)
#pragma unroll
        for (int j = 0; j < 5; j++) acc[i][j] = 0.f;

    for (int kc = 0; kc < DD; kc += 128) {
        const int k = kc + lane * 4;
        float4 a1[2], a2[2];
#pragma unroll
        for (int i = 0; i < 2; i++) {
            a1[i] = *(const float4*)(tn + ((size_t)(b0 + i) * TT + (size_t)t) * DD + k);
            a2[i] = *(const float4*)(&g_hbuf[par][b0 + i][k]);
        }
#pragma unroll
        for (int j = 0; j < 5; j++) {
            float4 w1 = *(const float4*)(W_tn + (size_t)(j0 + j) * DD + k);
            float4 w2 = *(const float4*)(W_pn + (size_t)(j0 + j) * DD + k);
#pragma unroll
            for (int i = 0; i < 2; i++) {
                float a = acc[i][j];
                a = fmaf(a1[i].x, w1.x, a); a = fmaf(a1[i].y, w1.y, a);
                a = fmaf(a1[i].z, w1.z, a); a = fmaf(a1[i].w, w1.w, a);
                a = fmaf(a2[i].x, w2.x, a); a = fmaf(a2[i].y, w2.y, a);
                a = fmaf(a2[i].z, w2.z, a); a = fmaf(a2[i].w, w2.w, a);
                acc[i][j] = a;
            }
        }
    }
#pragma unroll
    for (int i = 0; i < 2; i++)
#pragma unroll
        for (int j = 0; j < 5; j++) acc[i][j] = wred(acc[i][j]);

    if (lane == 0) {
#pragma unroll
        for (int i = 0; i < 2; i++)
#pragma unroll
            for (int j = 0; j < 5; j++)
                g_z[b0 + i][j0 + j] = tanhf(acc[i][j] + b_joint[j0 + j]);
    }
}

// ============================================================================
// L: logits for CTA's 8 v-columns; emit (max, sumexp, argmax) partial
// per (batch, CTA). Warp owns 2 batches.
// ============================================================================
__device__ __forceinline__ void l_phase(
    int cc, int wid, int lane,
    const float* __restrict__ W_out, const float* __restrict__ b_out)
{
    const int v0 = cc * 8;
    const int b0 = wid * 2;
    float acc[2][8];
#pragma unroll
    for (int i = 0; i < 2; i++)
#pragma unroll
        for (int v = 0; v < 8; v++) acc[i][v] = 0.f;

    for (int kc = 0; kc < DD; kc += 128) {
        const int k = kc + lane * 4;
        float4 zv[2];
#pragma unroll
        for (int i = 0; i < 2; i++) zv[i] = *(const float4*)(&g_z[b0 + i][k]);
#pragma unroll
        for (int v = 0; v < 8; v++) {
            float4 wv = *(const float4*)(W_out + (size_t)(v0 + v) * DD + k);
#pragma unroll
            for (int i = 0; i < 2; i++) {
                float a = acc[i][v];
                a = fmaf(zv[i].x, wv.x, a); a = fmaf(zv[i].y, wv.y, a);
                a = fmaf(zv[i].z, wv.z, a); a = fmaf(zv[i].w, wv.w, a);
                acc[i][v] = a;
            }
        }
    }
#pragma unroll
    for (int i = 0; i < 2; i++)
#pragma unroll
        for (int v = 0; v < 8; v++) acc[i][v] = wred(acc[i][v]);

    if (lane == 0) {
#pragma unroll
        for (int i = 0; i < 2; i++) {
            float vals[8];
#pragma unroll
            for (int v = 0; v < 8; v++) vals[v] = acc[i][v] + b_out[v0 + v];
            float m = vals[0]; int mi = v0;
#pragma unroll
            for (int v = 1; v < 8; v++)
                if (vals[v] > m) { m = vals[v]; mi = v0 + v; }  // lowest idx on tie
            float s = 0.f;
#pragma unroll
            for (int v = 0; v < 8; v++) s += expf(vals[v] - m);
            g_part[b0 + i][cc] = make_float4(m, s, (float)mi, 0.f);
        }
    }
}

// ============================================================================
// h-half of LSTM gates: sg[b][g] = h[b]·W_hh[g]  (token-independent; runs in
// phase B alongside l_phase for ILP). Warps: pass(2: gate-pairs) x bq(8: 4 b).
// ============================================================================
__device__ __forceinline__ void gh_half(
    int cc, int wid, int lane, int rp,
    const float* __restrict__ W_hh, float* sg)
{
    const int j0 = cc * 5;
    const int pass = wid >> 3;
    const int b0 = (wid & 7) * 4;
    float acc[4][10];
#pragma unroll
    for (int i = 0; i < 4; i++)
#pragma unroll
        for (int o = 0; o < 10; o++) acc[i][o] = 0.f;

#pragma unroll 1
    for (int kc = 0; kc < DD; kc += 128) {
        const int k = kc + lane * 4;
        float4 hv[4];
#pragma unroll
        for (int i = 0; i < 4; i++) hv[i] = *(const float4*)(&g_hbuf[rp][b0 + i][k]);
#pragma unroll
        for (int o = 0; o < 10; o++) {
            const int row = (pass * 2 + o / 5) * DD + j0 + (o % 5);
            float4 w = *(const float4*)(W_hh + (size_t)row * DD + k);
#pragma unroll
            for (int i = 0; i < 4; i++) {
                float a = acc[i][o];
                a = fmaf(hv[i].x, w.x, a); a = fmaf(hv[i].y, w.y, a);
                a = fmaf(hv[i].z, w.z, a); a = fmaf(hv[i].w, w.w, a);
                acc[i][o] = a;
            }
        }
    }
#pragma unroll
    for (int i = 0; i < 4; i++)
#pragma unroll
        for (int o = 0; o < 10; o++) {
            float r = wred(acc[i][o]);
            if (lane == 0) sg[(b0 + i) * 20 + pass * 10 + o] = r;
        }
}

// ============================================================================
// x-half of LSTM gates: sg[b][g] += E[tok[b]]·W_ih[g]. Same warp mapping.
// ============================================================================
__device__ __forceinline__ void gx_half(
    int cc, int wid, int lane,
    const float* __restrict__ E, const float* __restrict__ W_ih,
    float* sg, const int* s_tok)
{
    const int j0 = cc * 5;
    const int pass = wid >> 3;
    const int b0 = (wid & 7) * 4;
    float acc[4][10];
#pragma unroll
    for (int i = 0; i < 4; i++)
#pragma unroll
        for (int o = 0; o < 10; o++) acc[i][o] = 0.f;

    const float* xp[4];
#pragma unroll
    for (int i = 0; i < 4; i++) xp[i] = E + (size_t)s_tok[b0 + i] * DD;

#pragma unroll 1
    for (int kc = 0; kc < DD; kc += 128) {
        const int k = kc + lane * 4;
        float4 xv[4];
#pragma unroll
        for (int i = 0; i < 4; i++) xv[i] = *(const float4*)(xp[i] + k);
#pragma unroll
        for (int o = 0; o < 10; o++) {
            const int row = (pass * 2 + o / 5) * DD + j0 + (o % 5);
            float4 w = *(const float4*)(W_ih + (size_t)row * DD + k);
#pragma unroll
            for (int i = 0; i < 4; i++) {
                float a = acc[i][o];
                a = fmaf(xv[i].x, w.x, a); a = fmaf(xv[i].y, w.y, a);
                a = fmaf(xv[i].z, w.z, a); a = fmaf(xv[i].w, w.w, a);
                acc[i][o] = a;
            }
        }
    }
#pragma unroll
    for (int i = 0; i < 4; i++)
#pragma unroll
        for (int o = 0; o < 10; o++) {
            float r = wred(acc[i][o]);
            if (lane == 0) sg[(b0 + i) * 20 + pass * 10 + o] += r;
        }
}

// ============================================================================
// Merge: every CTA redundantly merges the 128 partials per batch (bitwise-
// deterministic) -> smem tok/nonblank; CTA 0 writes tokens + score.
// ============================================================================
__device__ __forceinline__ void merge_phase(
    int cc, int wid, int lane, int t,
    float* __restrict__ out, int* s_tok, int* s_nb)
{
#pragma unroll
    for (int bi = 0; bi < 2; bi++) {
        const int b = wid * 2 + bi;
        float4 q = g_part[b][lane];
        float m = q.x, s = q.y; int mi = (int)q.z;
#pragma unroll
        for (int r = 1; r < 4; r++) {
            float4 p = g_part[b][lane + 32 * r];
            pmerge(m, s, mi, p.x, p.y, (int)p.z);
        }
#pragma unroll
        for (int d = 16; d > 0; d >>= 1) {
            float m2 = __shfl_xor_sync(0xffffffffu, m, d);
            float s2 = __shfl_xor_sync(0xffffffffu, s, d);
            int   i2 = __shfl_xor_sync(0xffffffffu, mi, d);
            pmerge(m, s, mi, m2, s2, i2);
        }
        if (lane == 0) {
            const int nb = (mi != 0);
            s_nb[b] = nb;
            s_tok[b] = nb ? mi : 0;   // blank-step LSTM result is discarded
            if (cc == 0) {
                out[(size_t)b * TT + t] = nb ? (float)mi : 0.0f;
                if (nb) g_score[b] += -logf(s);  // logp at argmax
            }
        }
    }
}

// ============================================================================
// Pointwise LSTM update: warps 0-7, lanes 0-19 -> (batch, j) pairs.
// ============================================================================
__device__ __forceinline__ void pointwise(
    int cc, int wid, int lane, int rp,
    const float* __restrict__ b_lstm, const float* sg, const int* s_nb)
{
    const int j0 = cc * 5;
    if (wid < 8 && lane < 20) {
        const int i = lane / 5, jj = lane - i * 5;
        const int b = wid * 4 + i;
        const int j = j0 + jj;
        if (s_nb[b]) {
            float gi = sg[b * 20 + jj]      + b_lstm[j];
            float gf = sg[b * 20 + 5 + jj]  + b_lstm[DD + j];
            float gg = sg[b * 20 + 10 + jj] + b_lstm[2 * DD + j];
            float go = sg[b * 20 + 15 + jj] + b_lstm[3 * DD + j];
            float cn = sigf(gf) * g_c[b][j] + sigf(gi) * tanhf(gg);
            float hn = sigf(go) * tanhf(cn);
            g_c[b][j] = cn;
            g_hbuf[rp ^ 1][b][j] = hn;
        } else {
            g_hbuf[rp ^ 1][b][j] = g_hbuf[rp][b][j];
        }
    }
}

// L2-prefetch next step's tn slice for this warp's z-phase batches.
__device__ __forceinline__ void tn_prefetch(int wid, int lane, int t1,
                                            const float* __restrict__ tn)
{
    const int b0 = wid * 2;
#pragma unroll
    for (int q = lane; q < 40; q += 32) {
        const int sel = (q >= 20);
        const int b = b0 + sel;
        const int off = (q - sel * 20) * 32;
        const float* p = tn + ((size_t)b * TT + (size_t)t1) * DD + off;
        asm volatile("prefetch.global.L2 [%0];" :: "l"(p));
    }
}

// ============================================================================
// Persistent kernel: init -> prime -> 1000 x { Z | L+Gh | merge+Gx+pointwise }
// ============================================================================
__global__ void __launch_bounds__(NT, 1)
rnnt_decode_kernel(const float* __restrict__ tn,     const float* __restrict__ E,
                   const float* __restrict__ W_ih,   const float* __restrict__ W_hh,
                   const float* __restrict__ b_lstm, const float* __restrict__ W_tn,
                   const float* __restrict__ W_pn,   const float* __restrict__ b_joint,
                   const float* __restrict__ W_out,  const float* __restrict__ b_out,
                   float* __restrict__ out)
{
    __shared__ float sg[BB * 20];
    __shared__ int   s_tok[BB];
    __shared__ int   s_nb[BB];

    const int cc   = blockIdx.x;
    const int tid  = threadIdx.x;
    const int lane = tid & 31;
    const int wid  = tid >> 5;

    // ---- per-launch state init (deterministic across graph replays) ----
    for (int i = cc * NT + tid; i < BB * DD; i += NB * NT) {
        (&g_hbuf[0][0][0])[i] = 0.f;
        (&g_c[0][0])[i]       = 0.f;
    }
    if (cc == 0 && tid < BB) g_score[tid] = 0.f;
    grid_barrier();

    // ---- priming step: h,c = lstm(E[BLANK], 0, 0); h-half is 0 (h==0) ----
    for (int i = tid; i < BB * 20; i += NT) sg[i] = 0.f;
    if (wid == 0) { s_tok[lane] = 0; s_nb[lane] = 1; }
    __syncthreads();
    int par = 0;
    gx_half(cc, wid, lane, E, W_ih, sg, s_tok);
    __syncthreads();
    pointwise(cc, wid, lane, par, b_lstm, sg, s_nb);
    par = 1;
    grid_barrier();

    // ---- sequential decode ----
    for (int t = 0; t < TT; t++) {
        // Phase A: joint projection
        z_phase(cc, wid, lane, t, par, tn, W_tn, W_pn, b_joint);
        grid_barrier();

        // Phase B: logits GEMV + token-independent h-half of LSTM (ILP mix)
        if (t + 1 < TT) tn_prefetch(wid, lane, t + 1, tn);
        l_phase(cc, wid, lane, W_out, b_out);
        if (t < TT - 1) gh_half(cc, wid, lane, par, W_hh, sg);
        grid_barrier();

        // Phase C: merge -> x-half -> pointwise
        merge_phase(cc, wid, lane, t, out, s_tok, s_nb);
        __syncthreads();
        if (t < TT - 1) {
            gx_half(cc, wid, lane, E, W_ih, sg, s_tok);
            __syncthreads();
            pointwise(cc, wid, lane, par, b_lstm, sg, s_nb);
            par ^= 1;
            grid_barrier();
        }
    }

    // ---- epilogue: scores + mean(exp(score)) (CTA 0 owns g_score) ----
    __syncthreads();
    if (cc == 0) {
        if (tid < BB) out[(size_t)BB * TT + tid] = g_score[tid];
        if (tid == 0) {
            float s = 0.f;
            for (int b = 0; b < BB; b++) s += expf(g_score[b]);
            out[(size_t)BB * TT + BB] = s / (float)BB;
        }
    }
}

extern "C" void kernel_launch(void* const* d_in, const int* in_sizes, int n_in,
                              void* d_out, int out_size)
{
    (void)in_sizes; (void)n_in; (void)out_size;
    const float* tn      = (const float*)d_in[0];
    const float* E       = (const float*)d_in[1];
    const float* W_ih    = (const float*)d_in[2];
    const float* W_hh    = (const float*)d_in[3];
    const float* b_lstm  = (const float*)d_in[4];
    const float* W_tn    = (const float*)d_in[5];
    const float* W_pn    = (const float*)d_in[6];
    const float* b_joint = (const float*)d_in[7];
    const float* W_out   = (const float*)d_in[8];
    const float* b_out   = (const float*)d_in[9];
    float* out = (float*)d_out;

    rnnt_decode_kernel<<<NB, NT>>>(tn, E, W_ih, W_hh, b_lstm,
                                   W_tn, W_pn, b_joint, W_out, b_out, out);
}